// round 3
// baseline (speedup 1.0000x reference)
#include <cuda_runtime.h>
#include <cuda_bf16.h>
#include <cstdint>

// ============================================================================
// BlockSparseLinear: out[M=8192, N=4096] = x[M, K=4096] @ (W .* mask)^T + bias
// mask: 16x16 uniform blocks, ~10% nonzero.
//
// mma.sync (HMMA) bf16 block-sparse GEMM with 3-term hi/lo split:
//   out ~= xh*wh + xh*wl + xl*wh   (rel err ~1e-5)
//
// Kernels:
//   detect_mask    -> mask element width (1B vs 4B)  [validated R1]
//   build_slots    -> per (ng, kg): compacted present (ob, sub) pair table
//   prep_w_compact -> w present blocks -> bf16 hi/lo compacted scratch
//   bsgemm         -> CTA 64Mx512N, 512 thr; warp = 64Mx32N (2 obs);
//                     double-buffered k-chunks of 64, cp.async for w,
//                     on-the-fly x fp32->bf16 hi/lo conversion.
// ============================================================================

#define KDIM 4096
#define NDIM 4096
#define NG   8
#define NKG  64
#define WSLOT 36

// ---- smem layout (bytes) ----
#define XS_ROW   144                        // 64 k-elems bf16 (128B) + 16 pad
#define XS_SIZE  9216                       // 64 rows * 144
#define XS_OFF(buf, prec) (((buf) * 2 + (prec)) * XS_SIZE)   // 0..36863
#define WS_ROW   48
#define WS_PREC  768                        // 16 rows * 48
#define WS_SLOT  1536
#define WS_OFF(buf) (36864 + (buf) * (WSLOT * WS_SLOT))      // 36864..147455
#define EPI_ROW  144                        // 32 cols fp32 (128B) + 16 pad
#define EPI_OFF(w) ((w) * 9216)                              // 0..147455 (reuse)
#define SBIAS_OFF 147456
#define SMEM_BYTES 149504

// ---- device scratch ----
__device__ int g_mask_elt4;
__device__ unsigned char g_tbl[NG * NKG * 128];
__device__ int g_cnt[NG * NKG];
// compacted w: [ng*NKG+kg][slot<128][prec][16 oc][16 k] bf16  (1024B/slot)
__device__ __align__(16) __nv_bfloat16 g_wc[(size_t)NG * NKG * 128 * 512];

// ---------------------------------------------------------------------------
// PTX helpers (baseline ISA only — no tcgen05 on this toolchain target)
// ---------------------------------------------------------------------------
__device__ __forceinline__ uint32_t smem_u32(const void* p) {
    uint32_t a;
    asm("{ .reg .u64 t; cvta.to.shared.u64 t, %1; cvt.u32.u64 %0, t; }"
        : "=r"(a) : "l"(p));
    return a;
}
#define CP_ASYNC16(dst, src) \
    asm volatile("cp.async.cg.shared.global [%0], [%1], 16;" \
                 :: "r"(dst), "l"(src) : "memory")
#define CP_COMMIT() asm volatile("cp.async.commit_group;" ::: "memory")
#define CP_WAIT(n)  asm volatile("cp.async.wait_group %0;" :: "n"(n) : "memory")

__device__ __forceinline__ void ldsm4(uint32_t* r, uint32_t a) {
    asm volatile("ldmatrix.sync.aligned.m8n8.x4.shared.b16 {%0,%1,%2,%3}, [%4];"
                 : "=r"(r[0]), "=r"(r[1]), "=r"(r[2]), "=r"(r[3]) : "r"(a));
}
__device__ __forceinline__ void mma16816(float* c, const uint32_t* a,
                                         uint32_t b0, uint32_t b1) {
    asm volatile("mma.sync.aligned.m16n8k16.row.col.f32.bf16.bf16.f32 "
                 "{%0,%1,%2,%3}, {%4,%5,%6,%7}, {%8,%9}, {%0,%1,%2,%3};"
                 : "+f"(c[0]), "+f"(c[1]), "+f"(c[2]), "+f"(c[3])
                 : "r"(a[0]), "r"(a[1]), "r"(a[2]), "r"(a[3]), "r"(b0), "r"(b1));
}

// ---------------------------------------------------------------------------
// Mask dtype detection (validated R1)
// ---------------------------------------------------------------------------
__global__ void detect_mask_kernel(const unsigned char* __restrict__ mask) {
    __shared__ int s_gt1, s_pair;
    if (threadIdx.x == 0) { s_gt1 = 0; s_pair = 0; }
    __syncthreads();
    const int SCAN = 1 << 20;
    for (int i = threadIdx.x; i < SCAN; i += blockDim.x) {
        unsigned char a = mask[i];
        if (a > 1) s_gt1 = 1;
        if (a == 1 && mask[i + 1] == 1) s_pair = 1;
    }
    __syncthreads();
    if (threadIdx.x == 0) g_mask_elt4 = (s_gt1 || !s_pair) ? 1 : 0;
}

// ---------------------------------------------------------------------------
// Per (ng, kg) compacted present-pair tables. pair p = sub*32 + g.
// ---------------------------------------------------------------------------
__global__ void build_slots(const void* __restrict__ mask) {
    const int kg = blockIdx.x, ng = blockIdx.y;
    const int tid = threadIdx.x;          // 0..127
    const int sub = tid >> 5, g = tid & 31;
    const int ob = ng * 32 + g, kb = kg * 4 + sub;
    size_t e = (size_t)(ob * 16) * KDIM + (size_t)kb * 16;
    bool nz = g_mask_elt4 ? (((const unsigned*)mask)[e] != 0u)
                          : (((const unsigned char*)mask)[e] != 0);
    unsigned bal = __ballot_sync(0xFFFFFFFFu, nz);
    __shared__ int wc[4];
    if (g == 0) wc[sub] = __popc(bal);
    __syncthreads();
    int off = 0;
    for (int s = 0; s < sub; ++s) off += wc[s];
    int slot = off + __popc(bal & ((1u << g) - 1u));
    if (nz) g_tbl[(ng * NKG + kg) * 128 + slot] = (unsigned char)tid;
    if (tid == 0) g_cnt[ng * NKG + kg] = wc[0] + wc[1] + wc[2] + wc[3];
}

// ---------------------------------------------------------------------------
// Compact present w blocks into bf16 hi/lo scratch.
// (Mask uniform within block -> present block means all 256 elems kept; R1's
//  probe-only logic passed at fp32 rounding level, confirming uniformity.)
// ---------------------------------------------------------------------------
__global__ void prep_w_compact(const float* __restrict__ w) {
    const int kg = blockIdx.x, ng = blockIdx.y;
    const int idx = ng * NKG + kg;
    const int cnt = g_cnt[idx];
    const unsigned char* tbl = g_tbl + idx * 128;
    __nv_bfloat16* dst = g_wc + (size_t)idx * 128 * 512;
    for (int i = threadIdx.x; i < cnt * 256; i += 256) {
        int slot = i >> 8, e = i & 255;
        int oc = e >> 4, k = e & 15;
        int p = tbl[slot];
        int g = p & 31, sub = p >> 5;
        float v = w[(size_t)((ng * 32 + g) * 16 + oc) * KDIM + kg * 64 + sub * 16 + k];
        __nv_bfloat16 h = __float2bfloat16(v);
        __nv_bfloat16 l = __float2bfloat16(v - __bfloat162float(h));
        dst[slot * 512 + oc * 16 + k] = h;
        dst[slot * 512 + 256 + oc * 16 + k] = l;
    }
}

// ---------------------------------------------------------------------------
// Main block-sparse GEMM
// ---------------------------------------------------------------------------
#define PAIR_BODY(ACC)                                                        \
    do {                                                                      \
        _Pragma("unroll")                                                     \
        for (int mf = 0; mf < 4; ++mf) {                                      \
            uint32_t ah[4], al[4];                                            \
            uint32_t xa = xabase + mf * 16 * XS_ROW;                          \
            ldsm4(ah, xa);                                                    \
            ldsm4(al, xa + XS_SIZE);                                          \
            mma16816(&ACC[mf * 8],     ah, bh[0], bh[2]);                     \
            mma16816(&ACC[mf * 8],     ah, bl[0], bl[2]);                     \
            mma16816(&ACC[mf * 8],     al, bh[0], bh[2]);                     \
            mma16816(&ACC[mf * 8 + 4], ah, bh[1], bh[3]);                     \
            mma16816(&ACC[mf * 8 + 4], ah, bl[1], bl[3]);                     \
            mma16816(&ACC[mf * 8 + 4], al, bh[1], bh[3]);                     \
        }                                                                     \
    } while (0)

__global__ void __launch_bounds__(512, 1)
bsgemm(const float* __restrict__ x, const float* __restrict__ bias,
       float* __restrict__ out) {
    extern __shared__ __align__(1024) char smem[];
    const int ng = blockIdx.x;
    const int m0 = blockIdx.y * 64;
    const int tid = threadIdx.x, wid = tid >> 5, lane = tid & 31;
    const uint32_t sb = smem_u32(smem);
    const int tb = ng * NKG;

    if (tid < 512) ((float*)(smem + SBIAS_OFF))[tid] = bias[ng * 512 + tid];

    float accA[32], accB[32];
#pragma unroll
    for (int i = 0; i < 32; ++i) { accA[i] = 0.0f; accB[i] = 0.0f; }

    // ---- staging helpers ----
    auto stage_x = [&](int kg, int buf) {
        const float* xp = x + (size_t)m0 * KDIM + kg * 64;
        for (int i = tid; i < 1024; i += 512) {
            int row = i >> 4, c4 = i & 15;
            float4 v = *(const float4*)(xp + (size_t)row * KDIM + c4 * 4);
            __nv_bfloat16 h0 = __float2bfloat16(v.x), h1 = __float2bfloat16(v.y);
            __nv_bfloat16 h2 = __float2bfloat16(v.z), h3 = __float2bfloat16(v.w);
            __nv_bfloat16 l0 = __float2bfloat16(v.x - __bfloat162float(h0));
            __nv_bfloat16 l1 = __float2bfloat16(v.y - __bfloat162float(h1));
            __nv_bfloat16 l2 = __float2bfloat16(v.z - __bfloat162float(h2));
            __nv_bfloat16 l3 = __float2bfloat16(v.w - __bfloat162float(h3));
            uint2 ph, pl;
            ph.x = (uint32_t)__bfloat16_as_ushort(h0) | ((uint32_t)__bfloat16_as_ushort(h1) << 16);
            ph.y = (uint32_t)__bfloat16_as_ushort(h2) | ((uint32_t)__bfloat16_as_ushort(h3) << 16);
            pl.x = (uint32_t)__bfloat16_as_ushort(l0) | ((uint32_t)__bfloat16_as_ushort(l1) << 16);
            pl.y = (uint32_t)__bfloat16_as_ushort(l2) | ((uint32_t)__bfloat16_as_ushort(l3) << 16);
            *(uint2*)(smem + XS_OFF(buf, 0) + row * XS_ROW + c4 * 8) = ph;
            *(uint2*)(smem + XS_OFF(buf, 1) + row * XS_ROW + c4 * 8) = pl;
        }
    };
    auto stage_w_async = [&](int kg, int buf, int cnt) {
        const char* base = (const char*)g_wc + (size_t)(tb + kg) * 131072;
        int n = cnt * 64;
        for (int i = tid; i < n; i += 512) {
            int slot = i >> 6, r = i & 63;
            int prec = r >> 5, row = (r >> 1) & 15, half = r & 1;
            const char* src = base + slot * 1024 + prec * 512 + row * 32 + half * 16;
            uint32_t dst = sb + WS_OFF(buf) + slot * WS_SLOT + prec * WS_PREC +
                           row * WS_ROW + half * 16;
            CP_ASYNC16(dst, src);
        }
    };
    auto stage_w_sync = [&](int kg, int buf, int s0, int s1) {
        const char* base = (const char*)g_wc +
            ((size_t)(tb + kg) * 128 + s0) * 1024;
        int n = (s1 - s0) * 64;
        for (int i = tid; i < n; i += 512) {
            int slot = i >> 6, r = i & 63;
            int prec = r >> 5, row = (r >> 1) & 15, half = r & 1;
            uint4 v = *(const uint4*)(base + slot * 1024 + prec * 512 + row * 32 + half * 16);
            *(uint4*)(smem + WS_OFF(buf) + slot * WS_SLOT + prec * WS_PREC +
                      row * WS_ROW + half * 16) = v;
        }
    };
    auto compute = [&](int kg, int buf, int s0, int s1) {
        const unsigned char* tbl = g_tbl + (tb + kg) * 128 + s0;
        const int n = s1 - s0;
        for (int i = 0; i < n; ++i) {
            int p = tbl[i];
            int g = p & 31, sub = p >> 5;
            unsigned obl = (unsigned)(g - wid * 2);
            if (obl >= 2u) continue;
            uint32_t wsb = sb + WS_OFF(buf) + i * WS_SLOT +
                           (lane & 15) * WS_ROW + (lane >> 4) * 16;
            uint32_t bh[4], bl[4];
            ldsm4(bh, wsb);
            ldsm4(bl, wsb + WS_PREC);
            uint32_t xabase = sb + XS_OFF(buf, 0) + (lane & 15) * XS_ROW +
                              sub * 32 + (lane >> 4) * 16;
            if (obl == 0) PAIR_BODY(accA);
            else          PAIR_BODY(accB);
        }
    };

    // ---- prologue ----
    {
        int c0 = g_cnt[tb]; if (c0 > WSLOT) c0 = WSLOT;
        stage_x(0, 0);
        stage_w_async(0, 0, c0);
        CP_COMMIT();
    }

    // ---- main loop ----
    for (int kg = 0; kg < NKG; ++kg) {
        const int bufc = kg & 1;
        const int cnt = g_cnt[tb + kg];
        if (kg + 1 < NKG) {
            int cn = g_cnt[tb + kg + 1]; if (cn > WSLOT) cn = WSLOT;
            stage_x(kg + 1, bufc ^ 1);
            stage_w_async(kg + 1, bufc ^ 1, cn);
            CP_COMMIT();
            CP_WAIT(1);
        } else {
            CP_WAIT(0);
        }
        __syncthreads();
        int e = cnt < WSLOT ? cnt : WSLOT;
        compute(kg, bufc, 0, e);
        for (int s0 = WSLOT; s0 < cnt; s0 += WSLOT) {   // rare overflow path
            int s1 = cnt < s0 + WSLOT ? cnt : s0 + WSLOT;
            __syncthreads();
            stage_w_sync(kg, bufc, s0, s1);
            __syncthreads();
            compute(kg, bufc, s0, s1);
        }
        __syncthreads();
    }

    // ---- epilogue: acc -> smem (coalesce) -> gmem, add bias ----
#pragma unroll
    for (int mf = 0; mf < 4; ++mf) {
#pragma unroll
        for (int nf = 0; nf < 2; ++nf) {
            int row = mf * 16 + (lane >> 2);
            int col = nf * 8 + (lane & 3) * 2;
            char* bA = smem + EPI_OFF(wid) + col * 4;
            *(float2*)(bA + row * EPI_ROW) =
                make_float2(accA[mf * 8 + nf * 4 + 0], accA[mf * 8 + nf * 4 + 1]);
            *(float2*)(bA + (row + 8) * EPI_ROW) =
                make_float2(accA[mf * 8 + nf * 4 + 2], accA[mf * 8 + nf * 4 + 3]);
            char* bB = smem + EPI_OFF(wid) + (16 + col) * 4;
            *(float2*)(bB + row * EPI_ROW) =
                make_float2(accB[mf * 8 + nf * 4 + 0], accB[mf * 8 + nf * 4 + 1]);
            *(float2*)(bB + (row + 8) * EPI_ROW) =
                make_float2(accB[mf * 8 + nf * 4 + 2], accB[mf * 8 + nf * 4 + 3]);
        }
    }
    __syncwarp();
    const float* sbias = (const float*)(smem + SBIAS_OFF) + wid * 32;
#pragma unroll
    for (int pass = 0; pass < 16; ++pass) {
        int row = pass * 4 + (lane >> 3);
        int c4 = (lane & 7) * 4;
        float4 v = *(const float4*)(smem + EPI_OFF(wid) + row * EPI_ROW + c4 * 4);
        float4 b = *(const float4*)(sbias + c4);
        v.x += b.x; v.y += b.y; v.z += b.z; v.w += b.w;
        *(float4*)(out + (size_t)(m0 + row) * NDIM + ng * 512 + wid * 32 + c4) = v;
    }
}

// ---------------------------------------------------------------------------
extern "C" void kernel_launch(void* const* d_in, const int* in_sizes, int n_in,
                              void* d_out, int out_size) {
    const float* x    = (const float*)d_in[0];   // [8192, 4096] fp32
    const float* w    = (const float*)d_in[1];   // [4096, 4096] fp32
    const float* bias = (const float*)d_in[2];   // [4096] fp32
    const void*  mask = d_in[3];                 // [4096, 4096] bool/int/float
    float* out = (float*)d_out;                  // [8192, 4096] fp32

    const int M = in_sizes[0] / KDIM;            // 8192

    cudaFuncSetAttribute(bsgemm, cudaFuncAttributeMaxDynamicSharedMemorySize,
                         SMEM_BYTES);

    detect_mask_kernel<<<1, 256>>>((const unsigned char*)mask);
    build_slots<<<dim3(NKG, NG), 128>>>(mask);
    prep_w_compact<<<dim3(NKG, NG), 256>>>(w);
    bsgemm<<<dim3(NG, M / 64), 512, SMEM_BYTES>>>(x, bias, out);
}

// round 4
// speedup vs baseline: 1.5376x; 1.5376x over previous
#include <cuda_runtime.h>
#include <cuda_bf16.h>
#include <cstdint>

// ============================================================================
// BlockSparseLinear: out[M=8192, N=4096] = x[M, K=4096] @ (W .* mask)^T + bias
// mask: 16x16 uniform blocks, ~10% nonzero.
//
// Warp-autonomous HMMA design (no syncthreads, no smem in GEMM):
//   - per output block: compacted list of nonzero k-blocks
//   - w pre-converted to bf16 hi/lo in mma B-fragment layout (prep pass)
//   - x loaded fp32 from L2, split to bf16 hi/lo in-register
//   - 3-term product: xh*wh + xh*wl + xl*wh  (rel err ~1e-5)
//   - warp = 64 M x 16 N; CTA = 4 warps same ob (w shared via L1)
// ============================================================================

#define KDIM 4096
#define NDIM 4096
#define NOB  256

__device__ int g_mask_elt4;
__device__ int g_obcnt[NOB];
__device__ unsigned char g_oblist[NOB * 256];
// per ob, per slot: [hi: 32 lanes x uint4][lo: 32 lanes x uint4] = 1 KB/slot
__device__ __align__(16) uint4 g_wc4[(size_t)NOB * 256 * 64];

// ---------------------------------------------------------------------------
__device__ __forceinline__ void split2(float a, float b, uint32_t& h, uint32_t& l) {
    __nv_bfloat162 hh = __floats2bfloat162_rn(a, b);   // .x = a (low 16 bits)
    uint32_t hu = *reinterpret_cast<uint32_t*>(&hh);
    float af = __uint_as_float(hu << 16);
    float bf = __uint_as_float(hu & 0xFFFF0000u);
    __nv_bfloat162 ll = __floats2bfloat162_rn(a - af, b - bf);
    h = hu;
    l = *reinterpret_cast<uint32_t*>(&ll);
}

__device__ __forceinline__ void mma16816(float* c, const uint32_t* a,
                                         uint32_t b0, uint32_t b1) {
    asm volatile("mma.sync.aligned.m16n8k16.row.col.f32.bf16.bf16.f32 "
                 "{%0,%1,%2,%3}, {%4,%5,%6,%7}, {%8,%9}, {%0,%1,%2,%3};"
                 : "+f"(c[0]), "+f"(c[1]), "+f"(c[2]), "+f"(c[3])
                 : "r"(a[0]), "r"(a[1]), "r"(a[2]), "r"(a[3]), "r"(b0), "r"(b1));
}

// ---------------------------------------------------------------------------
// Mask dtype detection (validated R1/R3)
// ---------------------------------------------------------------------------
__global__ void detect_mask_kernel(const unsigned char* __restrict__ mask) {
    __shared__ int s_gt1, s_pair;
    if (threadIdx.x == 0) { s_gt1 = 0; s_pair = 0; }
    __syncthreads();
    const int SCAN = 1 << 20;
    for (int i = threadIdx.x; i < SCAN; i += blockDim.x) {
        unsigned char a = mask[i];
        if (a > 1) s_gt1 = 1;
        if (a == 1 && mask[i + 1] == 1) s_pair = 1;
    }
    __syncthreads();
    if (threadIdx.x == 0) g_mask_elt4 = (s_gt1 || !s_pair) ? 1 : 0;
}

// ---------------------------------------------------------------------------
// Per-output-block compacted nonzero k-block lists.
// ---------------------------------------------------------------------------
__global__ void build_slots(const void* __restrict__ mask) {
    const int ob = blockIdx.x;
    const int kb = threadIdx.x;   // 0..255
    size_t e = (size_t)(ob * 16) * KDIM + (size_t)kb * 16;
    bool nz = g_mask_elt4 ? (((const unsigned*)mask)[e] != 0u)
                          : (((const unsigned char*)mask)[e] != 0);
    unsigned bal = __ballot_sync(0xFFFFFFFFu, nz);
    __shared__ int wcnt[8];
    int wid = kb >> 5, lane = kb & 31;
    if (lane == 0) wcnt[wid] = __popc(bal);
    __syncthreads();
    int off = 0;
    for (int i = 0; i < wid; ++i) off += wcnt[i];
    if (nz)
        g_oblist[ob * 256 + off + __popc(bal & ((1u << lane) - 1u))] =
            (unsigned char)kb;
    if (kb == 0) {
        int tot = 0;
        for (int i = 0; i < 8; ++i) tot += wcnt[i];
        g_obcnt[ob] = tot;
    }
}

// ---------------------------------------------------------------------------
// Build w hi/lo bf16 in exact mma B-fragment layout.
//   K permutation (shared with x loads): logical k (2t,2t+1) -> phys (4t,4t+1),
//   logical (2t+8,2t+9) -> phys (4t+2,4t+3).  (sum over k is perm-invariant)
//   lane: g = lane>>2 (n within half), t = lane&3
//   hi uint4 = {nf0 b0, nf0 b1, nf1 b0, nf1 b1}, lo likewise.
// ---------------------------------------------------------------------------
__global__ void prep_w(const float* __restrict__ w) {
    const int ob = blockIdx.x;
    const int ws = threadIdx.x >> 5;   // 8 warps stride slots
    const int lane = threadIdx.x & 31;
    const int g = lane >> 2, t = lane & 3;
    const int cnt = g_obcnt[ob];
    uint4* dst = g_wc4 + (size_t)ob * 256 * 64;
    for (int s = ws; s < cnt; s += 8) {
        int kb = g_oblist[ob * 256 + s];
        const float* wr = w + (size_t)(ob * 16 + g) * KDIM + kb * 16 + t * 4;
        float4 v0 = *(const float4*)wr;              // n = g       (nf0)
        float4 v1 = *(const float4*)(wr + 8 * KDIM); // n = g + 8   (nf1)
        uint4 hi, lo;
        split2(v0.x, v0.y, hi.x, lo.x);
        split2(v0.z, v0.w, hi.y, lo.y);
        split2(v1.x, v1.y, hi.z, lo.z);
        split2(v1.z, v1.w, hi.w, lo.w);
        dst[(size_t)s * 64 + lane] = hi;
        dst[(size_t)s * 64 + 32 + lane] = lo;
    }
}

// ---------------------------------------------------------------------------
// Main GEMM: grid (256 obs, M/256), 128 threads (4 warps x 64 M rows).
// ---------------------------------------------------------------------------
__global__ void __launch_bounds__(128)
bsgemm(const float* __restrict__ x, const float* __restrict__ bias,
       float* __restrict__ out) {
    const int ob = blockIdx.x;
    const int m0 = blockIdx.y * 256 + (threadIdx.x >> 5) * 64;
    const int lane = threadIdx.x & 31;
    const int g = lane >> 2, t = lane & 3;

    float acc[32];
#pragma unroll
    for (int i = 0; i < 32; ++i) acc[i] = 0.0f;

    const int cnt = g_obcnt[ob];
    const unsigned char* lst = g_oblist + ob * 256;
    const uint4* wc = g_wc4 + (size_t)ob * 256 * 64;
    const float* xb = x + (size_t)(m0 + g) * KDIM + t * 4;

    for (int i = 0; i < cnt; ++i) {
        const int kb = lst[i];
        // ---- loads first (max MLP): 2x w LDG.128 + 8x x LDG.128 ----
        uint4 wh = wc[(size_t)i * 64 + lane];
        uint4 wl = wc[(size_t)i * 64 + 32 + lane];
        const float4* xp = (const float4*)(xb + kb * 16);
        float4 v[8];
#pragma unroll
        for (int mf = 0; mf < 4; ++mf) {
            v[mf * 2]     = xp[(size_t)(mf * 16) * (KDIM / 4)];
            v[mf * 2 + 1] = xp[(size_t)(mf * 16 + 8) * (KDIM / 4)];
        }
        // ---- convert + mma ----
#pragma unroll
        for (int mf = 0; mf < 4; ++mf) {
            uint32_t ah[4], al[4];
            split2(v[mf * 2].x,     v[mf * 2].y,     ah[0], al[0]);   // row g,   k lo
            split2(v[mf * 2].z,     v[mf * 2].w,     ah[2], al[2]);   // row g,   k hi
            split2(v[mf * 2 + 1].x, v[mf * 2 + 1].y, ah[1], al[1]);   // row g+8, k lo
            split2(v[mf * 2 + 1].z, v[mf * 2 + 1].w, ah[3], al[3]);   // row g+8, k hi
            float* cA = acc + mf * 8;
            float* cB = acc + mf * 8 + 4;
            mma16816(cA, ah, wh.x, wh.y);
            mma16816(cA, ah, wl.x, wl.y);
            mma16816(cA, al, wh.x, wh.y);
            mma16816(cB, ah, wh.z, wh.w);
            mma16816(cB, ah, wl.z, wl.w);
            mma16816(cB, al, wh.z, wh.w);
        }
    }

    // ---- epilogue: bias + direct STG.64 ----
    const float2 b0 = *(const float2*)(bias + ob * 16 + t * 2);
    const float2 b1 = *(const float2*)(bias + ob * 16 + 8 + t * 2);
#pragma unroll
    for (int mf = 0; mf < 4; ++mf) {
        const int r0 = m0 + mf * 16 + g;
        float* o0 = out + (size_t)r0 * NDIM + ob * 16 + t * 2;
        float* o1 = o0 + (size_t)8 * NDIM;
        *(float2*)o0       = make_float2(acc[mf * 8 + 0] + b0.x, acc[mf * 8 + 1] + b0.y);
        *(float2*)(o0 + 8) = make_float2(acc[mf * 8 + 4] + b1.x, acc[mf * 8 + 5] + b1.y);
        *(float2*)o1       = make_float2(acc[mf * 8 + 2] + b0.x, acc[mf * 8 + 3] + b0.y);
        *(float2*)(o1 + 8) = make_float2(acc[mf * 8 + 6] + b1.x, acc[mf * 8 + 7] + b1.y);
    }
}

// ---------------------------------------------------------------------------
extern "C" void kernel_launch(void* const* d_in, const int* in_sizes, int n_in,
                              void* d_out, int out_size) {
    const float* x    = (const float*)d_in[0];   // [8192, 4096] fp32
    const float* w    = (const float*)d_in[1];   // [4096, 4096] fp32
    const float* bias = (const float*)d_in[2];   // [4096] fp32
    const void*  mask = d_in[3];                 // [4096, 4096] bool/int/float
    float* out = (float*)d_out;                  // [8192, 4096] fp32

    const int M = in_sizes[0] / KDIM;            // 8192

    detect_mask_kernel<<<1, 256>>>((const unsigned char*)mask);
    build_slots<<<NOB, 256>>>(mask);
    prep_w<<<NOB, 256>>>(w);
    bsgemm<<<dim3(NOB, M / 256), 128>>>(x, bias, out);
}

// round 6
// speedup vs baseline: 10.4852x; 6.8190x over previous
#include <cuda_runtime.h>
#include <cuda_bf16.h>
#include <cstdint>

// ============================================================================
// BlockSparseLinear: out[M=8192, N=4096] = x[M, K=4096] @ (W .* mask)^T + bias
// mask: 16x16 uniform blocks, ~10% nonzero.
//
// R6 == R5 resubmit (R5 hit a GPU-broker timeout; kernel never ran):
//   - detect_mask parallelized (R4's single-block version cost 1.44 ms!)
//   - prep_x: x -> fragment-ordered bf16 hi/lo per (k-block, 16-row tile)
//   - prep_w: w present blocks -> bf16 hi/lo B-fragments (validated R4)
//   - bsgemm inner loop: 10 coalesced LDG.128 + 24 MMA, no conversion
//   - 3-term product xh*wh + xh*wl + xl*wh  (rel err ~5e-6, validated)
// ============================================================================

#define KDIM 4096
#define NDIM 4096
#define NOB  256

__device__ int g_gt1, g_pair;          // sticky detection flags (idempotent)
__device__ int g_obcnt[NOB];
__device__ unsigned char g_oblist[NOB * 256];
// w fragments: per ob, per slot: [hi: 32 x uint4][lo: 32 x uint4] = 1 KB
__device__ __align__(16) uint4 g_wc4[(size_t)NOB * 256 * 64];
// x fragments: per (kb, mtile16): [hi: 32 x uint4][lo: 32 x uint4] = 1 KB
__device__ __align__(16) uint4 g_xf[(size_t)256 * 512 * 64];

// ---------------------------------------------------------------------------
__device__ __forceinline__ void split2(float a, float b, uint32_t& h, uint32_t& l) {
    __nv_bfloat162 hh = __floats2bfloat162_rn(a, b);
    uint32_t hu = *reinterpret_cast<uint32_t*>(&hh);
    float af = __uint_as_float(hu << 16);
    float bf = __uint_as_float(hu & 0xFFFF0000u);
    __nv_bfloat162 ll = __floats2bfloat162_rn(a - af, b - bf);
    h = hu;
    l = *reinterpret_cast<uint32_t*>(&ll);
}

__device__ __forceinline__ void mma16816(float* c, const uint32_t* a,
                                         uint32_t b0, uint32_t b1) {
    asm volatile("mma.sync.aligned.m16n8k16.row.col.f32.bf16.bf16.f32 "
                 "{%0,%1,%2,%3}, {%4,%5,%6,%7}, {%8,%9}, {%0,%1,%2,%3};"
                 : "+f"(c[0]), "+f"(c[1]), "+f"(c[2]), "+f"(c[3])
                 : "r"(a[0]), "r"(a[1]), "r"(a[2]), "r"(a[3]), "r"(b0), "r"(b1));
}

// ---------------------------------------------------------------------------
// Mask dtype detection — PARALLEL (512 blocks; R4's 1-block version = 1.44 ms).
//  elt4 = any_byte>1 (float) || no adjacent 1-pairs (int32). Sticky atomicOr
//  flags are idempotent across graph replays (same input -> same bits).
// ---------------------------------------------------------------------------
__global__ void detect_mask_kernel(const unsigned char* __restrict__ mask) {
    size_t base = ((size_t)blockIdx.x * blockDim.x + threadIdx.x) * 8;
    uint64_t v = *(const uint64_t*)(mask + base);
    unsigned char nxt = mask[base + 8];
    bool gt1 = false, pair = false;
#pragma unroll
    for (int j = 0; j < 8; ++j) {
        unsigned char a = (unsigned char)(v >> (8 * j));
        unsigned char b = (j < 7) ? (unsigned char)(v >> (8 * (j + 1))) : nxt;
        gt1 |= (a > 1);
        pair |= (a == 1 && b == 1);
    }
    unsigned bg = __ballot_sync(0xFFFFFFFFu, gt1);
    unsigned bp = __ballot_sync(0xFFFFFFFFu, pair);
    if ((threadIdx.x & 31) == 0) {
        if (bg) atomicOr(&g_gt1, 1);
        if (bp) atomicOr(&g_pair, 1);
    }
}

// ---------------------------------------------------------------------------
// Per-output-block compacted nonzero k-block lists.
// ---------------------------------------------------------------------------
__global__ void build_slots(const void* __restrict__ mask) {
    const int ob = blockIdx.x;
    const int kb = threadIdx.x;   // 0..255
    const bool elt4 = (g_gt1 != 0) || (g_pair == 0);
    size_t e = (size_t)(ob * 16) * KDIM + (size_t)kb * 16;
    bool nz = elt4 ? (((const unsigned*)mask)[e] != 0u)
                   : (((const unsigned char*)mask)[e] != 0);
    unsigned bal = __ballot_sync(0xFFFFFFFFu, nz);
    __shared__ int wcnt[8];
    int wid = kb >> 5, lane = kb & 31;
    if (lane == 0) wcnt[wid] = __popc(bal);
    __syncthreads();
    int off = 0;
    for (int i = 0; i < wid; ++i) off += wcnt[i];
    if (nz)
        g_oblist[ob * 256 + off + __popc(bal & ((1u << lane) - 1u))] =
            (unsigned char)kb;
    if (kb == 0) {
        int tot = 0;
        for (int i = 0; i < 8; ++i) tot += wcnt[i];
        g_obcnt[ob] = tot;
    }
}

// ---------------------------------------------------------------------------
// w -> bf16 hi/lo B-fragments (validated R4; permuted-k convention).
//   lane: g = lane>>2 (n within half), t = lane&3
//   hi uint4 = {nf0 b0, nf0 b1, nf1 b0, nf1 b1}
// ---------------------------------------------------------------------------
__global__ void prep_w(const float* __restrict__ w) {
    const int ob = blockIdx.x;
    const int ws = threadIdx.x >> 5;
    const int lane = threadIdx.x & 31;
    const int g = lane >> 2, t = lane & 3;
    const int cnt = g_obcnt[ob];
    uint4* dst = g_wc4 + (size_t)ob * 256 * 64;
    for (int s = ws; s < cnt; s += 8) {
        int kb = g_oblist[ob * 256 + s];
        const float* wr = w + (size_t)(ob * 16 + g) * KDIM + kb * 16 + t * 4;
        float4 v0 = *(const float4*)wr;              // n = g       (nf0)
        float4 v1 = *(const float4*)(wr + 8 * KDIM); // n = g + 8   (nf1)
        uint4 hi, lo;
        split2(v0.x, v0.y, hi.x, lo.x);
        split2(v0.z, v0.w, hi.y, lo.y);
        split2(v1.x, v1.y, hi.z, lo.z);
        split2(v1.z, v1.w, hi.w, lo.w);
        dst[(size_t)s * 64 + lane] = hi;
        dst[(size_t)s * 64 + 32 + lane] = lo;
    }
}

// ---------------------------------------------------------------------------
// x -> bf16 hi/lo A-fragments, k-block-major.
//   Same permuted-k convention as R4's in-loop split (matches prep_w):
//   lane l (g=l>>2, t=l&3): a0 = rows mt*16+g,  k t*4..t*4+1
//                           a2 = rows mt*16+g,  k t*4+2..t*4+3
//                           a1/a3 = rows +8, same k
//   Tile (kb, mt): [hi 32 x uint4][lo 32 x uint4] contiguous 1 KB.
//   grid (256 kb, 64), 256 thr: 8 warps -> 8 mtiles.
// ---------------------------------------------------------------------------
__global__ void prep_x(const float* __restrict__ x) {
    const int kb = blockIdx.x;
    const int mt = blockIdx.y * 8 + (threadIdx.x >> 5);
    const int lane = threadIdx.x & 31;
    const int g = lane >> 2, t = lane & 3;
    const float* xr = x + (size_t)(mt * 16 + g) * KDIM + kb * 16 + t * 4;
    float4 v0 = *(const float4*)xr;                  // row g
    float4 v1 = *(const float4*)(xr + 8 * KDIM);     // row g+8
    uint4 hi, lo;
    split2(v0.x, v0.y, hi.x, lo.x);    // a0
    split2(v1.x, v1.y, hi.y, lo.y);    // a1
    split2(v0.z, v0.w, hi.z, lo.z);    // a2
    split2(v1.z, v1.w, hi.w, lo.w);    // a3
    uint4* dst = g_xf + ((size_t)kb * 512 + mt) * 64;
    dst[lane] = hi;
    dst[32 + lane] = lo;
}

// ---------------------------------------------------------------------------
// Main GEMM: grid (256 obs, M/256), 128 threads (4 warps x 64 M rows).
// Inner loop: 2 w LDG.128 + 8 x LDG.128 (all coalesced, fragment-ready) + 24 MMA.
// ---------------------------------------------------------------------------
__global__ void __launch_bounds__(128)
bsgemm(const float* __restrict__ bias, float* __restrict__ out) {
    const int ob = blockIdx.x;
    const int wid = threadIdx.x >> 5;
    const int m0 = blockIdx.y * 256 + wid * 64;
    const int mt0 = blockIdx.y * 16 + wid * 4;
    const int lane = threadIdx.x & 31;
    const int g = lane >> 2, t = lane & 3;

    float acc[32];
#pragma unroll
    for (int i = 0; i < 32; ++i) acc[i] = 0.0f;

    const int cnt = g_obcnt[ob];
    const unsigned char* lst = g_oblist + ob * 256;
    const uint4* wc = g_wc4 + (size_t)ob * 256 * 64;

    for (int i = 0; i < cnt; ++i) {
        const int kb = lst[i];
        // ---- loads first (max MLP) ----
        uint4 wh = wc[(size_t)i * 64 + lane];
        uint4 wl = wc[(size_t)i * 64 + 32 + lane];
        const uint4* xf = g_xf + ((size_t)kb * 512 + mt0) * 64;
        uint4 xh[4], xl[4];
#pragma unroll
        for (int tt = 0; tt < 4; ++tt) {
            xh[tt] = xf[tt * 64 + lane];
            xl[tt] = xf[tt * 64 + 32 + lane];
        }
        // ---- mma: 3-term hi/lo ----
#pragma unroll
        for (int mf = 0; mf < 4; ++mf) {
            const uint32_t* ah = reinterpret_cast<const uint32_t*>(&xh[mf]);
            const uint32_t* al = reinterpret_cast<const uint32_t*>(&xl[mf]);
            float* cA = acc + mf * 8;
            float* cB = acc + mf * 8 + 4;
            mma16816(cA, ah, wh.x, wh.y);
            mma16816(cA, ah, wl.x, wl.y);
            mma16816(cA, al, wh.x, wh.y);
            mma16816(cB, ah, wh.z, wh.w);
            mma16816(cB, ah, wl.z, wl.w);
            mma16816(cB, al, wh.z, wh.w);
        }
    }

    // ---- epilogue: bias + direct STG.64 (validated R4) ----
    const float2 b0 = *(const float2*)(bias + ob * 16 + t * 2);
    const float2 b1 = *(const float2*)(bias + ob * 16 + 8 + t * 2);
#pragma unroll
    for (int mf = 0; mf < 4; ++mf) {
        const int r0 = m0 + mf * 16 + g;
        float* o0 = out + (size_t)r0 * NDIM + ob * 16 + t * 2;
        float* o1 = o0 + (size_t)8 * NDIM;
        *(float2*)o0       = make_float2(acc[mf * 8 + 0] + b0.x, acc[mf * 8 + 1] + b0.y);
        *(float2*)(o0 + 8) = make_float2(acc[mf * 8 + 4] + b1.x, acc[mf * 8 + 5] + b1.y);
        *(float2*)o1       = make_float2(acc[mf * 8 + 2] + b0.x, acc[mf * 8 + 3] + b0.y);
        *(float2*)(o1 + 8) = make_float2(acc[mf * 8 + 6] + b1.x, acc[mf * 8 + 7] + b1.y);
    }
}

// ---------------------------------------------------------------------------
extern "C" void kernel_launch(void* const* d_in, const int* in_sizes, int n_in,
                              void* d_out, int out_size) {
    const float* x    = (const float*)d_in[0];   // [8192, 4096] fp32
    const float* w    = (const float*)d_in[1];   // [4096, 4096] fp32
    const float* bias = (const float*)d_in[2];   // [4096] fp32
    const void*  mask = d_in[3];                 // [4096, 4096] bool/int/float
    float* out = (float*)d_out;                  // [8192, 4096] fp32

    const int M = in_sizes[0] / KDIM;            // 8192

    detect_mask_kernel<<<512, 256>>>((const unsigned char*)mask);
    build_slots<<<NOB, 256>>>(mask);
    prep_w<<<NOB, 256>>>(w);
    prep_x<<<dim3(256, M / 128), 256>>>(x);
    bsgemm<<<dim3(NOB, M / 256), 128>>>(bias, out);
}

// round 7
// speedup vs baseline: 10.9805x; 1.0472x over previous
#include <cuda_runtime.h>
#include <cuda_bf16.h>
#include <cstdint>

// ============================================================================
// BlockSparseLinear: out[M=8192, N=4096] = x[M, K=4096] @ (W .* mask)^T + bias
// mask: 16x16 uniform blocks, ~10% nonzero.
//
// R7: R6 + software-pipelined bsgemm slot loop (prefetch next slot's
//     w/x fragments during current slot's MMAs; clamped indices, no branches).
//   - detect_mask parallel, build_slots, prep_w, prep_x: validated R6
//   - 3-term product xh*wh + xh*wl + xl*wh  (rel err 4.7e-6, validated)
// ============================================================================

#define KDIM 4096
#define NDIM 4096
#define NOB  256

__device__ int g_gt1, g_pair;          // sticky detection flags (idempotent)
__device__ int g_obcnt[NOB];
__device__ unsigned char g_oblist[NOB * 256];
// w fragments: per ob, per slot: [hi: 32 x uint4][lo: 32 x uint4] = 1 KB
__device__ __align__(16) uint4 g_wc4[(size_t)NOB * 256 * 64];
// x fragments: per (kb, mtile16): [hi: 32 x uint4][lo: 32 x uint4] = 1 KB
__device__ __align__(16) uint4 g_xf[(size_t)256 * 512 * 64];

// ---------------------------------------------------------------------------
__device__ __forceinline__ void split2(float a, float b, uint32_t& h, uint32_t& l) {
    __nv_bfloat162 hh = __floats2bfloat162_rn(a, b);
    uint32_t hu = *reinterpret_cast<uint32_t*>(&hh);
    float af = __uint_as_float(hu << 16);
    float bf = __uint_as_float(hu & 0xFFFF0000u);
    __nv_bfloat162 ll = __floats2bfloat162_rn(a - af, b - bf);
    h = hu;
    l = *reinterpret_cast<uint32_t*>(&ll);
}

__device__ __forceinline__ void mma16816(float* c, const uint32_t* a,
                                         uint32_t b0, uint32_t b1) {
    asm volatile("mma.sync.aligned.m16n8k16.row.col.f32.bf16.bf16.f32 "
                 "{%0,%1,%2,%3}, {%4,%5,%6,%7}, {%8,%9}, {%0,%1,%2,%3};"
                 : "+f"(c[0]), "+f"(c[1]), "+f"(c[2]), "+f"(c[3])
                 : "r"(a[0]), "r"(a[1]), "r"(a[2]), "r"(a[3]), "r"(b0), "r"(b1));
}

// ---------------------------------------------------------------------------
// Mask dtype detection — parallel (validated R6).
// ---------------------------------------------------------------------------
__global__ void detect_mask_kernel(const unsigned char* __restrict__ mask) {
    size_t base = ((size_t)blockIdx.x * blockDim.x + threadIdx.x) * 8;
    uint64_t v = *(const uint64_t*)(mask + base);
    unsigned char nxt = mask[base + 8];
    bool gt1 = false, pair = false;
#pragma unroll
    for (int j = 0; j < 8; ++j) {
        unsigned char a = (unsigned char)(v >> (8 * j));
        unsigned char b = (j < 7) ? (unsigned char)(v >> (8 * (j + 1))) : nxt;
        gt1 |= (a > 1);
        pair |= (a == 1 && b == 1);
    }
    unsigned bg = __ballot_sync(0xFFFFFFFFu, gt1);
    unsigned bp = __ballot_sync(0xFFFFFFFFu, pair);
    if ((threadIdx.x & 31) == 0) {
        if (bg) atomicOr(&g_gt1, 1);
        if (bp) atomicOr(&g_pair, 1);
    }
}

// ---------------------------------------------------------------------------
// Per-output-block compacted nonzero k-block lists (validated).
// ---------------------------------------------------------------------------
__global__ void build_slots(const void* __restrict__ mask) {
    const int ob = blockIdx.x;
    const int kb = threadIdx.x;   // 0..255
    const bool elt4 = (g_gt1 != 0) || (g_pair == 0);
    size_t e = (size_t)(ob * 16) * KDIM + (size_t)kb * 16;
    bool nz = elt4 ? (((const unsigned*)mask)[e] != 0u)
                   : (((const unsigned char*)mask)[e] != 0);
    unsigned bal = __ballot_sync(0xFFFFFFFFu, nz);
    __shared__ int wcnt[8];
    int wid = kb >> 5, lane = kb & 31;
    if (lane == 0) wcnt[wid] = __popc(bal);
    __syncthreads();
    int off = 0;
    for (int i = 0; i < wid; ++i) off += wcnt[i];
    if (nz)
        g_oblist[ob * 256 + off + __popc(bal & ((1u << lane) - 1u))] =
            (unsigned char)kb;
    if (kb == 0) {
        int tot = 0;
        for (int i = 0; i < 8; ++i) tot += wcnt[i];
        g_obcnt[ob] = tot;
    }
}

// ---------------------------------------------------------------------------
// w -> bf16 hi/lo B-fragments (validated; permuted-k convention).
// ---------------------------------------------------------------------------
__global__ void prep_w(const float* __restrict__ w) {
    const int ob = blockIdx.x;
    const int ws = threadIdx.x >> 5;
    const int lane = threadIdx.x & 31;
    const int g = lane >> 2, t = lane & 3;
    const int cnt = g_obcnt[ob];
    uint4* dst = g_wc4 + (size_t)ob * 256 * 64;
    for (int s = ws; s < cnt; s += 8) {
        int kb = g_oblist[ob * 256 + s];
        const float* wr = w + (size_t)(ob * 16 + g) * KDIM + kb * 16 + t * 4;
        float4 v0 = *(const float4*)wr;              // n = g       (nf0)
        float4 v1 = *(const float4*)(wr + 8 * KDIM); // n = g + 8   (nf1)
        uint4 hi, lo;
        split2(v0.x, v0.y, hi.x, lo.x);
        split2(v0.z, v0.w, hi.y, lo.y);
        split2(v1.x, v1.y, hi.z, lo.z);
        split2(v1.z, v1.w, hi.w, lo.w);
        dst[(size_t)s * 64 + lane] = hi;
        dst[(size_t)s * 64 + 32 + lane] = lo;
    }
}

// ---------------------------------------------------------------------------
// x -> bf16 hi/lo A-fragments, k-block-major (validated R6).
// ---------------------------------------------------------------------------
__global__ void prep_x(const float* __restrict__ x) {
    const int kb = blockIdx.x;
    const int mt = blockIdx.y * 8 + (threadIdx.x >> 5);
    const int lane = threadIdx.x & 31;
    const int g = lane >> 2, t = lane & 3;
    const float* xr = x + (size_t)(mt * 16 + g) * KDIM + kb * 16 + t * 4;
    float4 v0 = *(const float4*)xr;                  // row g
    float4 v1 = *(const float4*)(xr + 8 * KDIM);     // row g+8
    uint4 hi, lo;
    split2(v0.x, v0.y, hi.x, lo.x);    // a0
    split2(v1.x, v1.y, hi.y, lo.y);    // a1
    split2(v0.z, v0.w, hi.z, lo.z);    // a2
    split2(v1.z, v1.w, hi.w, lo.w);    // a3
    uint4* dst = g_xf + ((size_t)kb * 512 + mt) * 64;
    dst[lane] = hi;
    dst[32 + lane] = lo;
}

// ---------------------------------------------------------------------------
// Main GEMM: grid (256 obs, M/256), 128 threads (4 warps x 64 M rows).
// Software-pipelined: slot i+1's 10 LDG.128 issued before slot i's 24 MMAs.
// ---------------------------------------------------------------------------
__global__ void __launch_bounds__(128, 4)
bsgemm(const float* __restrict__ bias, float* __restrict__ out) {
    const int ob = blockIdx.x;
    const int wid = threadIdx.x >> 5;
    const int m0 = blockIdx.y * 256 + wid * 64;
    const int mt0 = blockIdx.y * 16 + wid * 4;
    const int lane = threadIdx.x & 31;
    const int g = lane >> 2, t = lane & 3;

    float acc[32];
#pragma unroll
    for (int i = 0; i < 32; ++i) acc[i] = 0.0f;

    const int cnt = g_obcnt[ob];
    const unsigned char* lst = g_oblist + ob * 256;
    const uint4* wc = g_wc4 + (size_t)ob * 256 * 64;

    // ---- prologue: load slot 0 (indices clamped; harmless if cnt==0) ----
    uint4 wh, wl, xh[4], xl[4];
    {
        const int kb0 = lst[0];
        wh = wc[lane];
        wl = wc[32 + lane];
        const uint4* xf = g_xf + ((size_t)kb0 * 512 + mt0) * 64;
#pragma unroll
        for (int tt = 0; tt < 4; ++tt) {
            xh[tt] = xf[tt * 64 + lane];
            xl[tt] = xf[tt * 64 + 32 + lane];
        }
    }

    for (int i = 0; i < cnt; ++i) {
        // ---- prefetch slot i+1 (clamped, stays in-bounds) ----
        const int ni = (i + 1 < cnt) ? (i + 1) : i;
        const int nkb = lst[ni];
        uint4 nwh = wc[(size_t)ni * 64 + lane];
        uint4 nwl = wc[(size_t)ni * 64 + 32 + lane];
        const uint4* nxf = g_xf + ((size_t)nkb * 512 + mt0) * 64;
        uint4 nxh[4], nxl[4];
#pragma unroll
        for (int tt = 0; tt < 4; ++tt) {
            nxh[tt] = nxf[tt * 64 + lane];
            nxl[tt] = nxf[tt * 64 + 32 + lane];
        }
        // ---- mma on current slot: 3-term hi/lo ----
#pragma unroll
        for (int mf = 0; mf < 4; ++mf) {
            const uint32_t* ah = reinterpret_cast<const uint32_t*>(&xh[mf]);
            const uint32_t* al = reinterpret_cast<const uint32_t*>(&xl[mf]);
            float* cA = acc + mf * 8;
            float* cB = acc + mf * 8 + 4;
            mma16816(cA, ah, wh.x, wh.y);
            mma16816(cA, ah, wl.x, wl.y);
            mma16816(cA, al, wh.x, wh.y);
            mma16816(cB, ah, wh.z, wh.w);
            mma16816(cB, ah, wl.z, wl.w);
            mma16816(cB, al, wh.z, wh.w);
        }
        // ---- rotate ----
        wh = nwh; wl = nwl;
#pragma unroll
        for (int tt = 0; tt < 4; ++tt) { xh[tt] = nxh[tt]; xl[tt] = nxl[tt]; }
    }

    // ---- epilogue: bias + direct STG.64 (validated) ----
    const float2 b0 = *(const float2*)(bias + ob * 16 + t * 2);
    const float2 b1 = *(const float2*)(bias + ob * 16 + 8 + t * 2);
#pragma unroll
    for (int mf = 0; mf < 4; ++mf) {
        const int r0 = m0 + mf * 16 + g;
        float* o0 = out + (size_t)r0 * NDIM + ob * 16 + t * 2;
        float* o1 = o0 + (size_t)8 * NDIM;
        *(float2*)o0       = make_float2(acc[mf * 8 + 0] + b0.x, acc[mf * 8 + 1] + b0.y);
        *(float2*)(o0 + 8) = make_float2(acc[mf * 8 + 4] + b1.x, acc[mf * 8 + 5] + b1.y);
        *(float2*)o1       = make_float2(acc[mf * 8 + 2] + b0.x, acc[mf * 8 + 3] + b0.y);
        *(float2*)(o1 + 8) = make_float2(acc[mf * 8 + 6] + b1.x, acc[mf * 8 + 7] + b1.y);
    }
}

// ---------------------------------------------------------------------------
extern "C" void kernel_launch(void* const* d_in, const int* in_sizes, int n_in,
                              void* d_out, int out_size) {
    const float* x    = (const float*)d_in[0];   // [8192, 4096] fp32
    const float* w    = (const float*)d_in[1];   // [4096, 4096] fp32
    const float* bias = (const float*)d_in[2];   // [4096] fp32
    const void*  mask = d_in[3];                 // [4096, 4096] bool/int/float
    float* out = (float*)d_out;                  // [8192, 4096] fp32

    const int M = in_sizes[0] / KDIM;            // 8192

    detect_mask_kernel<<<512, 256>>>((const unsigned char*)mask);
    build_slots<<<NOB, 256>>>(mask);
    prep_w<<<NOB, 256>>>(w);
    prep_x<<<dim3(256, M / 128), 256>>>(x);
    bsgemm<<<dim3(NOB, M / 256), 128>>>(bias, out);
}